// round 10
// baseline (speedup 1.0000x reference)
#include <cuda_runtime.h>
#include <cuda_bf16.h>

// Sparsemax over rows: x, mask are [8192, 4096] fp32; out fp32 same shape.
// z = (mask ? x : NEG_BIG) * 2 ; tau solves sum(relu(z - tau)) = 1 ;
// out = relu(z - tau)  (mask multiply implied: masked z is hugely negative).
//
// R10: tau >= zmax - 1 => support lies in {z > zmax - 1} (typically 1-6
// elements). Each warp gathers its own candidates into a PRIVATE 16-slot
// shared segment (warp-scan slot assignment, sentinel-filled before the max
// barrier), so a row costs only TWO __syncthreads total. Every warp then
// redundantly runs a barrier-free warp-local Newton over all 128 slots.
// Block-uniform fallback to the proven block-Newton on overflow.

#define ROWS 8192
#define COLS 4096
#define THREADS 256
#define NWARPS (THREADS / 32)
#define ELEMS (COLS / THREADS)   // 16 floats per thread
#define VEC (ELEMS / 4)          // 4 float4 per thread
#define WCAP 16                  // candidate slots per warp
#define CAP (NWARPS * WCAP)      // 128 total (4 per lane)

__global__ __launch_bounds__(THREADS, 5)
void sparsemax_kernel(const float* __restrict__ x,
                      const float* __restrict__ m,
                      float* __restrict__ out) {
    const int row = blockIdx.x;
    const int t   = threadIdx.x;
    const int lane = t & 31;
    const int wid  = t >> 5;

    const float4* __restrict__ xr = reinterpret_cast<const float4*>(x + (size_t)row * COLS);
    const float4* __restrict__ mr = reinterpret_cast<const float4*>(m + (size_t)row * COLS);
    float4* __restrict__ orow     = reinterpret_cast<float4*>(out + (size_t)row * COLS);

    __shared__ float shmax[NWARPS];
    __shared__ int   wcount[NWARPS];
    __shared__ float cand[CAP];
    __shared__ float fs[2][NWARPS];   // fallback double-buffer (sum)
    __shared__ int   fc[2][NWARPS];   // fallback double-buffer (count)

    // ---- Front-batch ALL loads (8 x LDG.128 in flight per thread) ----
    float4 xv[VEC];
    float4 mv[VEC];
#pragma unroll
    for (int v = 0; v < VEC; v++) xv[v] = xr[t + v * THREADS];
#pragma unroll
    for (int v = 0; v < VEC; v++) mv[v] = mr[t + v * THREADS];

    // Pre-initialize this warp's candidate segment (ordered by barrier 1).
    if (lane < WCAP) cand[wid * WCAP + lane] = -3.0e38f;

    // ---- Apply mask + temperature, track local max ----
    float z[ELEMS];
    float vmax = -3.0e38f;
    const float NEGZ = -9999999.9f * 2.0f;  // masked value after temperature
#pragma unroll
    for (int v = 0; v < VEC; v++) {
        float z0 = (mv[v].x != 0.0f) ? (xv[v].x * 2.0f) : NEGZ;
        float z1 = (mv[v].y != 0.0f) ? (xv[v].y * 2.0f) : NEGZ;
        float z2 = (mv[v].z != 0.0f) ? (xv[v].z * 2.0f) : NEGZ;
        float z3 = (mv[v].w != 0.0f) ? (xv[v].w * 2.0f) : NEGZ;
        z[v * 4 + 0] = z0;
        z[v * 4 + 1] = z1;
        z[v * 4 + 2] = z2;
        z[v * 4 + 3] = z3;
        vmax = fmaxf(vmax, fmaxf(fmaxf(z0, z1), fmaxf(z2, z3)));
    }

    // ---- Block max reduction ----
#pragma unroll
    for (int o = 16; o > 0; o >>= 1)
        vmax = fmaxf(vmax, __shfl_xor_sync(0xFFFFFFFFu, vmax, o));
    if (lane == 0) shmax[wid] = vmax;
    __syncthreads();                       // barrier 1
    float zmax = -3.0e38f;
#pragma unroll
    for (int i = 0; i < NWARPS; i++) zmax = fmaxf(zmax, shmax[i]);

    const float T0 = zmax - 1.0f;

    // ---- Warp-local candidate gather (slots via warp scan only) ----
    int lc = 0;
#pragma unroll
    for (int e = 0; e < ELEMS; e++) lc += (z[e] > T0) ? 1 : 0;

    int inc = lc;                          // inclusive prefix over lanes
#pragma unroll
    for (int o = 1; o < 32; o <<= 1) {
        int v = __shfl_up_sync(0xFFFFFFFFu, inc, o);
        if (lane >= o) inc += v;
    }
    int off = inc - lc;                    // exclusive prefix = my first slot
    const int wtot = __shfl_sync(0xFFFFFFFFu, inc, 31);
    if (lane == 0) wcount[wid] = wtot;

#pragma unroll
    for (int e = 0; e < ELEMS; e++) {
        if (z[e] > T0 && off < WCAP) cand[wid * WCAP + off++] = z[e];
    }
    __syncthreads();                       // barrier 2 (last barrier)

    bool ovf = false;
#pragma unroll
    for (int i = 0; i < NWARPS; i++) ovf |= (wcount[i] > WCAP);

    float tau;
    if (!ovf) {
        // ---- Warp-local Newton (every warp redundantly; identical tau) ----
        float c0 = cand[lane +  0];
        float c1 = cand[lane + 32];
        float c2 = cand[lane + 64];
        float c3 = cand[lane + 96];

        float T = T0;
#pragma unroll 1
        for (int it = 0; it < 32; ++it) {
            float s = 0.0f, c = 0.0f;
            float d;
            d = c0 - T; if (d > 0.0f) { s += d; c += 1.0f; }
            d = c1 - T; if (d > 0.0f) { s += d; c += 1.0f; }
            d = c2 - T; if (d > 0.0f) { s += d; c += 1.0f; }
            d = c3 - T; if (d > 0.0f) { s += d; c += 1.0f; }
#pragma unroll
            for (int o = 16; o > 0; o >>= 1) {
                s += __shfl_xor_sync(0xFFFFFFFFu, s, o);
                c += __shfl_xor_sync(0xFFFFFFFFu, c, o);
            }
            if (c < 0.5f) break;           // can't happen (zmax is a candidate)
            float delta = __fdividef(s - 1.0f, c);
            T += delta;
            if (fabsf(delta) < 1e-6f) break;
        }
        tau = T;
    } else {
        // ---- Fallback: proven block-Newton (block-uniform branch) ----
        float T = T0;
#pragma unroll 1
        for (int it = 0; it < 32; ++it) {
            const int b = it & 1;
            float s = 0.0f;
            int   c = 0;
#pragma unroll
            for (int e = 0; e < ELEMS; e++) {
                float d = z[e] - T;
                if (d > 0.0f) { s += d; c += 1; }
            }
#pragma unroll
            for (int o = 16; o > 0; o >>= 1) {
                s += __shfl_xor_sync(0xFFFFFFFFu, s, o);
                c += __shfl_xor_sync(0xFFFFFFFFu, c, o);
            }
            if (lane == 0) { fs[b][wid] = s; fc[b][wid] = c; }
            __syncthreads();
            float S = 0.0f;
            int   C = 0;
#pragma unroll
            for (int i = 0; i < NWARPS; i++) { S += fs[b][i]; C += fc[b][i]; }

            if (C == 0) break;
            float delta = __fdividef(S - 1.0f, (float)C);
            T += delta;
            if (fabsf(delta) < 1e-6f) break;
        }
        tau = T;
    }

    // ---- Output: relu(z - tau). Masked entries are ~-2e7, relu -> 0. ----
#pragma unroll
    for (int v = 0; v < VEC; v++) {
        float4 ov;
        ov.x = fmaxf(0.0f, z[v * 4 + 0] - tau);
        ov.y = fmaxf(0.0f, z[v * 4 + 1] - tau);
        ov.z = fmaxf(0.0f, z[v * 4 + 2] - tau);
        ov.w = fmaxf(0.0f, z[v * 4 + 3] - tau);
        orow[t + v * THREADS] = ov;
    }
}

extern "C" void kernel_launch(void* const* d_in, const int* in_sizes, int n_in,
                              void* d_out, int out_size) {
    const float* x = (const float*)d_in[0];
    const float* m = (const float*)d_in[1];
    float* out = (float*)d_out;
    sparsemax_kernel<<<ROWS, THREADS>>>(x, m, out);
}